// round 1
// baseline (speedup 1.0000x reference)
#include <cuda_runtime.h>
#include <math.h>

#define BB   2
#define CC   48
#define HH   128
#define WW   256
#define HWW  (HH*WW)          // 32768
#define C3   144
#define C2   96
#define NH   3
#define CHD  16

// ---------------- scratch (static device globals; no allocation) ----------------
__device__ float g_qkv_pre [2][BB][C3][HWW];   // after LN + 1x1 qkv
__device__ float g_qkv_post[2][BB][C3][HWW];   // after depthwise 3x3
__device__ float g_qfold   [BB][CC][HWW];      // fused dilated-conv + convQ output
__device__ float g_weff    [C2*27*CC];         // folded weights, layout [ic][d*9+k][o]
__device__ float g_beff    [CC];
__device__ float g_inv     [3][BB][CC];        // 0: Qfold  1: K_l  2: K_r  (1/max(||.||,eps))
__device__ float g_dpart   [2*BB*NH*16*256];   // QK dot partials over 16 p-chunks
__device__ float g_M       [2*BB*CC*CC];       // folded conv1/2 @ blockdiag(A)

// ---------------- weight folding: W_eff = convQ x dil_w ----------------
__global__ void k_fold_w(const float* __restrict__ qw, const float* __restrict__ d0,
                         const float* __restrict__ d1, const float* __restrict__ d2) {
    int o = blockIdx.x;        // 0..47
    int d = blockIdx.y;        // 0..2
    const float* dw = (d == 0) ? d0 : (d == 1) ? d1 : d2;
    __shared__ float qr[C2];
    for (int j = threadIdx.x; j < C2; j += blockDim.x)
        qr[j] = qw[o*(3*C2) + d*C2 + j];
    __syncthreads();
    for (int ik = threadIdx.x; ik < C2*9; ik += blockDim.x) {
        float acc = 0.f;
        for (int j = 0; j < C2; ++j)
            acc += qr[j] * dw[j*(C2*9) + ik];
        int i = ik / 9, k = ik - i*9;
        g_weff[(i*27 + d*9 + k)*CC + o] = acc;
    }
}

__global__ void k_fold_b(const float* __restrict__ qw, const float* __restrict__ qb,
                         const float* __restrict__ b0, const float* __restrict__ b1,
                         const float* __restrict__ b2) {
    int o = threadIdx.x;
    if (o < CC) {
        float acc = qb[o];
        for (int j = 0; j < C2; ++j) {
            acc += qw[o*288 +       j] * b0[j];
            acc += qw[o*288 +  96 + j] * b1[j];
            acc += qw[o*288 + 192 + j] * b2[j];
        }
        g_beff[o] = acc;
    }
}

// ---------------- fused LayerNorm2d + 1x1 qkv (48 -> 144) ----------------
__global__ void k_ln_qkv(const float* __restrict__ xl, const float* __restrict__ xr,
                         const float* __restrict__ ln1w, const float* __restrict__ ln1b,
                         const float* __restrict__ ln2w, const float* __restrict__ ln2b,
                         const float* __restrict__ wl, const float* __restrict__ bl,
                         const float* __restrict__ wr, const float* __restrict__ brb) {
    int branch = blockIdx.z, b = blockIdx.y;
    int p = blockIdx.x * blockDim.x + threadIdx.x;
    const float* x    = (branch == 0 ? xl : xr) + b*CC*HWW;
    const float* lw   = branch == 0 ? ln1w : ln2w;
    const float* lb   = branch == 0 ? ln1b : ln2b;
    const float* w    = branch == 0 ? wl : wr;
    const float* bias = branch == 0 ? bl : brb;
    float* out = &g_qkv_pre[branch][b][0][0];

    __shared__ __align__(16) float ws[C3*CC];
    __shared__ float bs[C3];
    __shared__ float lws[CC], lbs[CC];
    for (int i = threadIdx.x; i < C3*CC; i += blockDim.x) ws[i] = w[i];
    for (int i = threadIdx.x; i < C3; i += blockDim.x)    bs[i] = bias[i];
    for (int i = threadIdx.x; i < CC; i += blockDim.x)  { lws[i] = lw[i]; lbs[i] = lb[i]; }
    __syncthreads();

    float y[CC];
    float mu = 0.f;
    #pragma unroll
    for (int c = 0; c < CC; ++c) { y[c] = x[c*HWW + p]; mu += y[c]; }
    mu *= (1.f/CC);
    float var = 0.f;
    #pragma unroll
    for (int c = 0; c < CC; ++c) { float t = y[c] - mu; var += t*t; }
    var *= (1.f/CC);
    float rstd = rsqrtf(var + 1e-6f);
    #pragma unroll
    for (int c = 0; c < CC; ++c) y[c] = (y[c] - mu)*rstd*lws[c] + lbs[c];

    for (int o = 0; o < C3; ++o) {
        float acc = bs[o];
        const float4* w4 = reinterpret_cast<const float4*>(&ws[o*CC]);
        #pragma unroll
        for (int c4 = 0; c4 < CC/4; ++c4) {
            float4 wv = w4[c4];
            acc += wv.x*y[4*c4] + wv.y*y[4*c4+1] + wv.z*y[4*c4+2] + wv.w*y[4*c4+3];
        }
        out[o*HWW + p] = acc;
    }
}

// ---------------- depthwise 3x3, pad 1 ----------------
__global__ void k_dw(const float* __restrict__ wl, const float* __restrict__ bl,
                     const float* __restrict__ wr, const float* __restrict__ brb) {
    int z = blockIdx.z; int branch = z >> 1, b = z & 1;
    int ch = blockIdx.y, y = blockIdx.x, x = threadIdx.x;
    const float* in = &g_qkv_pre[branch][b][ch][0];
    const float* w  = (branch == 0 ? wl : wr) + ch*9;
    float acc = (branch == 0 ? bl : brb)[ch];
    #pragma unroll
    for (int ky = 0; ky < 3; ++ky) {
        int yy = y + ky - 1;
        if (yy < 0 || yy >= HH) continue;
        #pragma unroll
        for (int kx = 0; kx < 3; ++kx) {
            int xx = x + kx - 1;
            if (xx < 0 || xx >= WW) continue;
            acc += w[ky*3+kx] * in[yy*WW + xx];
        }
    }
    g_qkv_post[branch][b][ch][y*WW + x] = acc;
}

// ---------------- fused dilated convs (2/4/6) + convQ: Qc[96] -> Qfold[48] ----------------
// block: 256 threads = 8 oc-groups x 32 lanes; tile = 48 oc x 128 px (one row segment)
__global__ void k_dilated() {
    __shared__ float ins[4][7][144];            // 4 in-ch x 7 rows x (128+12 halo, padded)
    __shared__ __align__(16) float ws[4*27*CC]; // [ic][tap][o]
    int x0 = blockIdx.x * 128;
    int y  = blockIdx.y;
    int b  = blockIdx.z;
    int tid = threadIdx.x;
    int lane = tid & 31, ot = tid >> 5;
    int o0 = ot * 6;
    const float* pl = &g_qkv_post[0][b][0][0];
    const float* pr = &g_qkv_post[1][b][0][0];

    float acc[6][4];
    #pragma unroll
    for (int j = 0; j < 6; ++j)
        #pragma unroll
        for (int q = 0; q < 4; ++q) acc[j][q] = 0.f;

    for (int cb = 0; cb < C2; cb += 4) {
        __syncthreads();
        // weights: contiguous copy of 4*27*48 floats
        const float4* wsrc = reinterpret_cast<const float4*>(&g_weff[cb*27*CC]);
        float4* wdst = reinterpret_cast<float4*>(ws);
        for (int i = tid; i < (4*27*CC)/4; i += 256) wdst[i] = wsrc[i];
        // inputs with zero-padded halo
        for (int idx = tid; idx < 4*7*144; idx += 256) {
            int ic  = idx / (7*144);
            int rem = idx - ic*(7*144);
            int r   = rem / 144;
            int col = rem - r*144;
            int gy = y + 2*r - 6;
            int gx = x0 + col - 6;
            float v = 0.f;
            if (col < 140 && gx >= 0 && gx < WW && gy >= 0 && gy < HH) {
                int icg = cb + ic;
                v = (icg < CC) ? pl[icg*HWW + gy*WW + gx]
                               : pr[(icg-CC)*HWW + gy*WW + gx];
            }
            ins[ic][r][col] = v;
        }
        __syncthreads();

        #pragma unroll
        for (int icl = 0; icl < 4; ++icl) {
            #pragma unroll
            for (int d = 0; d < 3; ++d) {
                const int dil = 2*(d+1);
                #pragma unroll
                for (int ky = 0; ky < 3; ++ky) {
                    const float* rp = &ins[icl][3 + (ky-1)*(d+1)][6 + lane];
                    #pragma unroll
                    for (int kx = 0; kx < 3; ++kx) {
                        const int off = (kx-1)*dil;
                        float a0 = rp[off], a1 = rp[off+32], a2 = rp[off+64], a3 = rp[off+96];
                        const float* wp = &ws[(icl*27 + d*9 + ky*3 + kx)*CC + o0];
                        #pragma unroll
                        for (int j = 0; j < 6; ++j) {
                            float wv = wp[j];
                            acc[j][0] += wv*a0; acc[j][1] += wv*a1;
                            acc[j][2] += wv*a2; acc[j][3] += wv*a3;
                        }
                    }
                }
            }
        }
    }

    int pbase = y*WW + x0 + lane;
    #pragma unroll
    for (int j = 0; j < 6; ++j) {
        int o = o0 + j;
        float be = g_beff[o];
        #pragma unroll
        for (int q = 0; q < 4; ++q)
            g_qfold[b][o][pbase + 32*q] = acc[j][q] + be;
    }
}

// ---------------- per-channel L2 norms over HW ----------------
__global__ void k_norms() {
    int gid = blockIdx.x;
    int t = gid / (BB*CC);
    int r = gid - t*(BB*CC);
    int b = r / CC, c = r - b*CC;
    const float* src;
    if (t == 0)      src = &g_qfold[b][c][0];
    else if (t == 1) src = &g_qkv_post[0][b][CC + c][0];
    else             src = &g_qkv_post[1][b][CC + c][0];
    float ss = 0.f;
    const float4* s4 = reinterpret_cast<const float4*>(src);
    for (int i = threadIdx.x; i < HWW/4; i += blockDim.x) {
        float4 v = s4[i];
        ss += v.x*v.x + v.y*v.y + v.z*v.z + v.w*v.w;
    }
    #pragma unroll
    for (int off = 16; off > 0; off >>= 1)
        ss += __shfl_down_sync(0xffffffffu, ss, off);
    __shared__ float red[8];
    if ((threadIdx.x & 31) == 0) red[threadIdx.x >> 5] = ss;
    __syncthreads();
    if (threadIdx.x == 0) {
        float tot = 0.f;
        for (int i = 0; i < (int)(blockDim.x >> 5); ++i) tot += red[i];
        float n = sqrtf(tot);
        g_inv[t][b][c] = 1.f / fmaxf(n, 1e-12f);
    }
}

// ---------------- QK^T dot partials (deterministic two-stage) ----------------
__global__ void k_dots() {
    int chunk = blockIdx.x;        // 0..15
    int bh    = blockIdx.y;        // 0..5
    int s     = blockIdx.z;        // 0: Q.K_r (for left out), 1: Q.K_l
    int b = bh / NH, h = bh - b*NH;
    const float* Q = &g_qfold[b][h*CHD][0];
    const float* K = (s == 0) ? &g_qkv_post[1][b][CC + h*CHD][0]
                              : &g_qkv_post[0][b][CC + h*CHD][0];
    __shared__ float Qs[16][257];
    __shared__ float Ks[16][257];
    int tid = threadIdx.x;
    int cq = tid >> 4, ck = tid & 15;
    float acc = 0.f;
    int p0 = chunk * 2048;
    for (int sub = 0; sub < 8; ++sub) {
        __syncthreads();
        int pb = p0 + sub*256;
        #pragma unroll
        for (int e = 0; e < 16; ++e) {
            Qs[e][tid] = Q[e*HWW + pb + tid];
            Ks[e][tid] = K[e*HWW + pb + tid];
        }
        __syncthreads();
        #pragma unroll 16
        for (int i = 0; i < 256; ++i)
            acc += Qs[cq][i] * Ks[ck][i];
    }
    g_dpart[(((s*BB + b)*NH + h)*16 + chunk)*256 + tid] = acc;
}

// ---------------- softmax + fold conv1/2 into M = w @ blockdiag(A) ----------------
__global__ void k_soft_m(const float* __restrict__ temp,
                         const float* __restrict__ w1, const float* __restrict__ w2) {
    __shared__ float As[192][16];
    int tid = threadIdx.x;
    if (tid < 192) {
        int s = tid / 96, rem = tid - s*96;
        int b = rem / 48, rem2 = rem - b*48;
        int h = rem2 / 16, cq = rem2 - h*16;
        float v[16];
        #pragma unroll
        for (int ck = 0; ck < 16; ++ck) v[ck] = 0.f;
        int base = (((s*BB + b)*NH + h)*16)*256 + cq*16;
        for (int chunk = 0; chunk < 16; ++chunk) {
            #pragma unroll
            for (int ck = 0; ck < 16; ++ck)
                v[ck] += g_dpart[base + chunk*256 + ck];
        }
        float iq = g_inv[0][b][h*16 + cq];
        float tm = temp[h];
        const float* ik = (s == 0) ? &g_inv[2][b][h*16] : &g_inv[1][b][h*16];
        float mx = -1e30f;
        #pragma unroll
        for (int ck = 0; ck < 16; ++ck) { v[ck] *= iq * ik[ck] * tm; mx = fmaxf(mx, v[ck]); }
        float sum = 0.f;
        #pragma unroll
        for (int ck = 0; ck < 16; ++ck) { v[ck] = expf(v[ck] - mx); sum += v[ck]; }
        float inv = 1.f / sum;
        #pragma unroll
        for (int ck = 0; ck < 16; ++ck) As[tid][ck] = v[ck] * inv;
    }
    __syncthreads();
    for (int idx = tid; idx < 2*BB*CC*CC; idx += blockDim.x) {
        int s = idx / (BB*CC*CC), rem = idx - s*(BB*CC*CC);
        int b = rem / (CC*CC), rem2 = rem - b*(CC*CC);
        int o = rem2 / CC, dg = rem2 - o*CC;
        int h = dg / 16, dd = dg - h*16;
        const float* wv = ((s == 0) ? w1 : w2) + o*CC + h*16;
        int arow = s*96 + b*48 + h*16;
        float acc = 0.f;
        #pragma unroll
        for (int c = 0; c < 16; ++c)
            acc += wv[c] * As[arow + c][dd];
        g_M[idx] = acc;
    }
}

// ---------------- epilogue: out = x + M @ V + bias ----------------
__global__ void k_epilogue(const float* __restrict__ xl, const float* __restrict__ xr,
                           const float* __restrict__ b1, const float* __restrict__ b2,
                           float* __restrict__ out) {
    int s = blockIdx.z, b = blockIdx.y;
    int p = blockIdx.x * blockDim.x + threadIdx.x;
    __shared__ __align__(16) float Ms[CC*CC];
    __shared__ float bs[CC];
    const float* Mg = &g_M[(s*BB + b)*CC*CC];
    for (int i = threadIdx.x; i < CC*CC; i += blockDim.x) Ms[i] = Mg[i];
    for (int i = threadIdx.x; i < CC; i += blockDim.x) bs[i] = (s == 0 ? b1 : b2)[i];
    __syncthreads();
    const float* V = &g_qkv_post[s == 0 ? 0 : 1][b][2*CC][0];
    const float* x = (s == 0 ? xl : xr) + b*CC*HWW;
    float* o = out + (s*BB + b)*CC*HWW;
    float v[CC];
    #pragma unroll
    for (int c = 0; c < CC; ++c) v[c] = V[c*HWW + p];
    for (int oc = 0; oc < CC; ++oc) {
        float acc = bs[oc];
        const float4* m4 = reinterpret_cast<const float4*>(&Ms[oc*CC]);
        #pragma unroll
        for (int c4 = 0; c4 < CC/4; ++c4) {
            float4 mv = m4[c4];
            acc += mv.x*v[4*c4] + mv.y*v[4*c4+1] + mv.z*v[4*c4+2] + mv.w*v[4*c4+3];
        }
        o[oc*HWW + p] = x[oc*HWW + p] + acc;
    }
}

// ---------------- launch ----------------
extern "C" void kernel_launch(void* const* d_in, const int* in_sizes, int n_in,
                              void* d_out, int out_size) {
    const float* x_l    = (const float*)d_in[0];
    const float* x_r    = (const float*)d_in[1];
    const float* ln1_w  = (const float*)d_in[2];
    const float* ln1_b  = (const float*)d_in[3];
    const float* ln2_w  = (const float*)d_in[4];
    const float* ln2_b  = (const float*)d_in[5];
    const float* qkvl_w = (const float*)d_in[6];
    const float* qkvl_b = (const float*)d_in[7];
    const float* qkvr_w = (const float*)d_in[8];
    const float* qkvr_b = (const float*)d_in[9];
    const float* dwl_w  = (const float*)d_in[10];
    const float* dwl_b  = (const float*)d_in[11];
    const float* dwr_w  = (const float*)d_in[12];
    const float* dwr_b  = (const float*)d_in[13];
    const float* dil0_w = (const float*)d_in[14];
    const float* dil0_b = (const float*)d_in[15];
    const float* dil1_w = (const float*)d_in[16];
    const float* dil1_b = (const float*)d_in[17];
    const float* dil2_w = (const float*)d_in[18];
    const float* dil2_b = (const float*)d_in[19];
    const float* convQ_w = (const float*)d_in[20];
    const float* convQ_b = (const float*)d_in[21];
    const float* conv1_w = (const float*)d_in[22];
    const float* conv1_b = (const float*)d_in[23];
    const float* conv2_w = (const float*)d_in[24];
    const float* conv2_b = (const float*)d_in[25];
    const float* temperature = (const float*)d_in[26];

    k_fold_w<<<dim3(CC, 3), 256>>>(convQ_w, dil0_w, dil1_w, dil2_w);
    k_fold_b<<<1, 64>>>(convQ_w, convQ_b, dil0_b, dil1_b, dil2_b);
    k_ln_qkv<<<dim3(HWW/128, BB, 2), 128>>>(x_l, x_r, ln1_w, ln1_b, ln2_w, ln2_b,
                                            qkvl_w, qkvl_b, qkvr_w, qkvr_b);
    k_dw<<<dim3(HH, C3, 2*BB), WW>>>(dwl_w, dwl_b, dwr_w, dwr_b);
    k_dilated<<<dim3(2, HH, BB), 256>>>();
    k_norms<<<3*BB*CC, 256>>>();
    k_dots<<<dim3(16, BB*NH, 2), 256>>>();
    k_soft_m<<<1, 256>>>(temperature, conv1_w, conv2_w);
    k_epilogue<<<dim3(HWW/256, BB, 2), 256>>>(x_l, x_r, conv1_b, conv2_b, (float*)d_out);
}